// round 3
// baseline (speedup 1.0000x reference)
#include <cuda_runtime.h>
#include <math.h>

#define B_    8
#define C_    512
#define N_    2048
#define KH    9
#define PAD   4
#define MLPH  2048

// ---------------- scratch (device globals: no allocations allowed) ----------
__device__ float g_qln[B_ * C_ * N_];
__device__ float g_kln[B_ * C_ * N_];
__device__ float g_qp [B_ * C_ * N_];
__device__ float g_kp [B_ * C_ * N_];
__device__ float g_vp [B_ * C_ * N_];
__device__ float g_xln[B_ * C_ * N_];
__device__ float g_h  [B_ * MLPH * N_];

// ---------------- fused (optional add) + channel LayerNorm ------------------
// LN is over channels at fixed (b, n). Layout [B, C, N]: one thread per n,
// loop over c -> every load coalesced across the 256-thread block.
template<bool HASE>
__global__ void add_ln_kernel(const float* __restrict__ x,
                              const float* __restrict__ e,
                              const float* __restrict__ g,
                              const float* __restrict__ bb,
                              float* __restrict__ out) {
    int n = blockIdx.x * blockDim.x + threadIdx.x;
    int b = blockIdx.y;
    const size_t base = (size_t)b * C_ * N_ + n;
    float s = 0.f, s2 = 0.f;
#pragma unroll 8
    for (int c = 0; c < C_; c++) {
        float v = x[base + (size_t)c * N_];
        if (HASE) v += e[base + (size_t)c * N_];
        s += v; s2 += v * v;
    }
    float mean = s * (1.f / C_);
    float var  = s2 * (1.f / C_) - mean * mean;
    float inv  = rsqrtf(var + 1e-5f);
#pragma unroll 8
    for (int c = 0; c < C_; c++) {
        float v = x[base + (size_t)c * N_];
        if (HASE) v += e[base + (size_t)c * N_];
        out[base + (size_t)c * N_] = (v - mean) * inv * __ldg(&g[c]) + __ldg(&bb[c]);
    }
}

// ---------------- tiled SGEMM:  Y[b,m,n] = sum_k W[m,k or k,m] * X[b,k,n] ---
// BM=128, BN=64, BK=16, 256 threads, 8x4 per-thread tile.
// WT=false: W is [M,K] row-major (conv weights [out_c,in_c]).
// WT=true : W is [K,M] row-major (MLP weights w1 [C,MLPH], w2 [MLPH,C]).
// EPI: 0 = +bias, 1 = gelu(+bias) exact, 2 = +bias + residual(res).
template<bool WT, int EPI>
__global__ __launch_bounds__(256)
void gemm_kernel(const float* __restrict__ W, const float* __restrict__ X,
                 const float* __restrict__ bias, const float* __restrict__ res,
                 float* __restrict__ Y, int M, int N, int K) {
    const int BM = 128, BN = 64, BK = 16;
    __shared__ float As[BK][BM + 4];   // +4 keeps float4 alignment, breaks worst conflicts
    __shared__ float Bs[BK][BN + 4];

    int t  = threadIdx.x;
    int n0 = blockIdx.x * BN;
    int m0 = blockIdx.y * BM;
    int b  = blockIdx.z;
    const float* Xb = X + (size_t)b * K * N;

    float acc[8][4];
#pragma unroll
    for (int i = 0; i < 8; i++)
#pragma unroll
        for (int j = 0; j < 4; j++) acc[i][j] = 0.f;

    int tm0 = (t >> 4) << 3;   // (t/16)*8
    int tn0 = (t & 15) << 2;   // (t%16)*4

    for (int k0 = 0; k0 < K; k0 += BK) {
        if (WT) {
#pragma unroll
            for (int i = 0; i < 8; i++) {
                int m  = t & 127;
                int kk = (i << 1) + (t >> 7);
                As[kk][m] = W[(size_t)(k0 + kk) * M + m0 + m];   // coalesced on m
            }
        } else {
#pragma unroll
            for (int i = 0; i < 8; i++) {
                int kk = t & 15;
                int m  = (i << 4) + (t >> 4);
                As[kk][m] = W[(size_t)(m0 + m) * K + k0 + kk];   // 16-wide segments
            }
        }
#pragma unroll
        for (int i = 0; i < 4; i++) {
            int n  = t & 63;
            int kk = (i << 2) + (t >> 6);
            Bs[kk][n] = Xb[(size_t)(k0 + kk) * N + n0 + n];      // coalesced on n
        }
        __syncthreads();
#pragma unroll
        for (int kk = 0; kk < BK; kk++) {
            float4 a0 = *(const float4*)&As[kk][tm0];
            float4 a1 = *(const float4*)&As[kk][tm0 + 4];
            float4 b0 = *(const float4*)&Bs[kk][tn0];
            float ar[8] = {a0.x, a0.y, a0.z, a0.w, a1.x, a1.y, a1.z, a1.w};
            float br[4] = {b0.x, b0.y, b0.z, b0.w};
#pragma unroll
            for (int i = 0; i < 8; i++)
#pragma unroll
                for (int j = 0; j < 4; j++)
                    acc[i][j] += ar[i] * br[j];
        }
        __syncthreads();
    }

    float* Yb = Y + (size_t)b * M * N;
    const float* Rb = (EPI == 2) ? res + (size_t)b * M * N : nullptr;
#pragma unroll
    for (int i = 0; i < 8; i++) {
        int m = m0 + tm0 + i;
        float bv = __ldg(&bias[m]);
#pragma unroll
        for (int j = 0; j < 4; j++) {
            int n = n0 + tn0 + j;
            float v = acc[i][j] + bv;
            if (EPI == 1) v = 0.5f * v * (1.f + erff(v * 0.70710678118654752f)); // exact gelu
            if (EPI == 2) v += Rb[(size_t)m * N + n];
            Yb[(size_t)m * N + n] = v;
        }
    }
}

// ---------------- fused windowed attention ----------------------------------
// Per block: batch b, 128 consecutive n. Phase 1: w[n,j] = sum_c q[c,n]*k[c,n+j-4]
// Phase 2: softmax(w)*scale, then out[c,n] = query[c,n] + sum_j w[j]*v[c,n+j-4]
__global__ __launch_bounds__(128)
void attn_kernel(const float* __restrict__ q, const float* __restrict__ k,
                 const float* __restrict__ v, const float* __restrict__ query,
                 float* __restrict__ out) {
    __shared__ float s1[8][128];
    __shared__ float s2[8][136];
    int tid = threadIdx.x;
    int n0  = blockIdx.x * 128;
    int b   = blockIdx.y;
    int n   = n0 + tid;
    const size_t base = (size_t)b * C_ * N_;

    float acc[KH];
#pragma unroll
    for (int j = 0; j < KH; j++) acc[j] = 0.f;

    for (int c0 = 0; c0 < C_; c0 += 8) {
#pragma unroll
        for (int j = 0; j < 8; j++) {
            s1[j][tid] = q[base + (size_t)(c0 + j) * N_ + n];
            int nn = n0 + tid - PAD;
            s2[j][tid] = (nn >= 0 && nn < N_) ? k[base + (size_t)(c0 + j) * N_ + nn] : 0.f;
        }
        if (tid < 8) {
#pragma unroll
            for (int j = 0; j < 8; j++) {
                int nn = n0 + 128 + tid - PAD;
                s2[j][128 + tid] = (nn < N_) ? k[base + (size_t)(c0 + j) * N_ + nn] : 0.f;
            }
        }
        __syncthreads();
#pragma unroll
        for (int cc = 0; cc < 8; cc++) {
            float qv = s1[cc][tid];
#pragma unroll
            for (int j = 0; j < KH; j++) acc[j] += qv * s2[cc][tid + j];
        }
        __syncthreads();
    }

    // softmax over KH, then * C^-0.5 (faithful: softmax first, scale after)
    float mx = acc[0];
#pragma unroll
    for (int j = 1; j < KH; j++) mx = fmaxf(mx, acc[j]);
    float sum = 0.f;
#pragma unroll
    for (int j = 0; j < KH; j++) { acc[j] = expf(acc[j] - mx); sum += acc[j]; }
    float inv = 0.044194173824159216f / sum;   // 512^-0.5 / sum
#pragma unroll
    for (int j = 0; j < KH; j++) acc[j] *= inv;

    for (int c0 = 0; c0 < C_; c0 += 8) {
#pragma unroll
        for (int j = 0; j < 8; j++) {
            int nn = n0 + tid - PAD;
            s2[j][tid] = (nn >= 0 && nn < N_) ? v[base + (size_t)(c0 + j) * N_ + nn] : 0.f;
        }
        if (tid < 8) {
#pragma unroll
            for (int j = 0; j < 8; j++) {
                int nn = n0 + 128 + tid - PAD;
                s2[j][128 + tid] = (nn < N_) ? v[base + (size_t)(c0 + j) * N_ + nn] : 0.f;
            }
        }
        __syncthreads();
#pragma unroll
        for (int cc = 0; cc < 8; cc++) {
            float r = 0.f;
#pragma unroll
            for (int j = 0; j < KH; j++) r += acc[j] * s2[cc][tid + j];
            size_t idx = base + (size_t)(c0 + cc) * N_ + n;
            out[idx] = query[idx] + r;
        }
        __syncthreads();
    }
}

// ---------------- launch -----------------------------------------------------
extern "C" void kernel_launch(void* const* d_in, const int* in_sizes, int n_in,
                              void* d_out, int out_size) {
    const float* query = (const float*)d_in[0];
    const float* key   = (const float*)d_in[1];
    const float* qe    = (const float*)d_in[2];
    const float* ke    = (const float*)d_in[3];
    const float* wq    = (const float*)d_in[4];
    const float* bq    = (const float*)d_in[5];
    const float* wk    = (const float*)d_in[6];
    const float* bk    = (const float*)d_in[7];
    const float* wv    = (const float*)d_in[8];
    const float* bv    = (const float*)d_in[9];
    const float* gn    = (const float*)d_in[10];
    const float* bn    = (const float*)d_in[11];
    const float* gn2   = (const float*)d_in[12];
    const float* bn2   = (const float*)d_in[13];
    const float* w1    = (const float*)d_in[14];
    const float* b1    = (const float*)d_in[15];
    const float* w2    = (const float*)d_in[16];
    const float* b2    = (const float*)d_in[17];
    float* out = (float*)d_out;

    float *qln, *kln, *qp, *kp, *vp, *xln, *hbuf;
    cudaGetSymbolAddress((void**)&qln,  g_qln);
    cudaGetSymbolAddress((void**)&kln,  g_kln);
    cudaGetSymbolAddress((void**)&qp,   g_qp);
    cudaGetSymbolAddress((void**)&kp,   g_kp);
    cudaGetSymbolAddress((void**)&vp,   g_vp);
    cudaGetSymbolAddress((void**)&xln,  g_xln);
    cudaGetSymbolAddress((void**)&hbuf, g_h);

    dim3 lnGrid(N_ / 256, B_);
    // 1) q/k: add pos-embed + shared LayerNorm
    add_ln_kernel<true><<<lnGrid, 256>>>(query, qe, gn, bn, qln);
    add_ln_kernel<true><<<lnGrid, 256>>>(key,   ke, gn, bn, kln);

    // 2) 1x1 convs (v uses RAW key)
    dim3 convGrid(N_ / 64, C_ / 128, B_);
    gemm_kernel<false, 0><<<convGrid, 256>>>(wq, qln, bq, nullptr, qp, C_, N_, C_);
    gemm_kernel<false, 0><<<convGrid, 256>>>(wk, kln, bk, nullptr, kp, C_, N_, C_);
    gemm_kernel<false, 0><<<convGrid, 256>>>(wv, key, bv, nullptr, vp, C_, N_, C_);

    // 3) windowed attention + residual  -> d_out holds x
    attn_kernel<<<dim3(N_ / 128, B_), 128>>>(qp, kp, vp, query, out);

    // 4) MLP: pre-LN, fc1+gelu, fc2+residual
    add_ln_kernel<false><<<lnGrid, 256>>>(out, nullptr, gn2, bn2, xln);
    gemm_kernel<true, 1><<<dim3(N_ / 64, MLPH / 128, B_), 256>>>(w1, xln,  b1, nullptr, hbuf, MLPH, N_, C_);
    gemm_kernel<true, 2><<<dim3(N_ / 64, C_   / 128, B_), 256>>>(w2, hbuf, b2, out,     out,  C_,   N_, MLPH);
}

// round 8
// speedup vs baseline: 1.3847x; 1.3847x over previous
#include <cuda_runtime.h>
#include <math.h>

#define B_    8
#define C_    512
#define N_    2048
#define KH    9
#define PAD   4
#define MLPH  2048

// ---------------- scratch (device globals: no allocations allowed) ----------
__device__ float g_qln[B_ * C_ * N_];
__device__ float g_kln[B_ * C_ * N_];
__device__ float g_qp [B_ * C_ * N_];
__device__ float g_kp [B_ * C_ * N_];
__device__ float g_vp [B_ * C_ * N_];
__device__ float g_xln[B_ * C_ * N_];
__device__ float g_h  [B_ * MLPH * N_];

// ---------------- fused (optional add) + channel LayerNorm ------------------
template<bool HASE>
__global__ void add_ln_kernel(const float* __restrict__ x,
                              const float* __restrict__ e,
                              const float* __restrict__ g,
                              const float* __restrict__ bb,
                              float* __restrict__ out) {
    int n = blockIdx.x * blockDim.x + threadIdx.x;
    int b = blockIdx.y;
    const size_t base = (size_t)b * C_ * N_ + n;
    float s = 0.f, s2 = 0.f;
#pragma unroll 8
    for (int c = 0; c < C_; c++) {
        float v = x[base + (size_t)c * N_];
        if (HASE) v += e[base + (size_t)c * N_];
        s += v; s2 += v * v;
    }
    float mean = s * (1.f / C_);
    float var  = s2 * (1.f / C_) - mean * mean;
    float inv  = rsqrtf(var + 1e-5f);
#pragma unroll 8
    for (int c = 0; c < C_; c++) {
        float v = x[base + (size_t)c * N_];
        if (HASE) v += e[base + (size_t)c * N_];
        out[base + (size_t)c * N_] = (v - mean) * inv * __ldg(&g[c]) + __ldg(&bb[c]);
    }
}

// ---------------- TF32 tensor-core GEMM -------------------------------------
// Y[b,m,n] = sum_k W[m,k] (WT=false) or W[k,m] (WT=true)  *  X[b,k,n]
// BM=BN=128, BK=16. 256 threads = 8 warps (2x4), warp tile 64x32,
// per warp 4x4 grid of mma.m16n8k8 (tf32 in, fp32 accum).
// EPI: 0 = +bias, 1 = gelu(+bias) exact, 2 = +bias + residual.

__device__ __forceinline__ unsigned f2tf(float x) {
    unsigned r; asm("cvt.rna.tf32.f32 %0, %1;" : "=r"(r) : "f"(x)); return r;
}

template<bool WT, int EPI>
__global__ __launch_bounds__(256)
void gemm_tc(const float* __restrict__ W, const float* __restrict__ X,
             const float* __restrict__ bias, const float* __restrict__ res,
             float* __restrict__ Y, int M, int N, int K) {
    const int BM = 128, BN = 128, BK = 16;
    const int LDS_ = 136;                       // 136 % 32 == 8 -> conflict-free frags
    __shared__ unsigned As[BK][LDS_];           // tf32 bits, [k][m]
    __shared__ unsigned Bs[BK][LDS_];           // tf32 bits, [k][n]

    int t    = threadIdx.x;
    int lane = t & 31;
    int warp = t >> 5;
    int gid  = lane >> 2;                       // 0..7
    int tig  = lane & 3;                        // 0..3
    int wm   = (warp & 1) * 64;                 // warp row offset in tile
    int wn   = (warp >> 1) * 32;                // warp col offset in tile

    int n0 = blockIdx.x * BN;
    int m0 = blockIdx.y * BM;
    int b  = blockIdx.z;
    const float* Xb = X + (size_t)b * K * N;

    float c[4][4][4];
#pragma unroll
    for (int i = 0; i < 4; i++)
#pragma unroll
        for (int j = 0; j < 4; j++)
#pragma unroll
            for (int r = 0; r < 4; r++) c[i][j][r] = 0.f;

    for (int k0 = 0; k0 < K; k0 += BK) {
        // ---- load A tile (128 x 16) ----
        if (WT) {       // W[K,M]: rows k, contiguous m -> direct float4
#pragma unroll
            for (int i = 0; i < 2; i++) {
                int idx = t + 256 * i;          // 0..511
                int kk  = idx >> 5;             // 0..15
                int mq  = (idx & 31) << 2;      // 0..124
                float4 w = *(const float4*)&W[(size_t)(k0 + kk) * M + m0 + mq];
                As[kk][mq + 0] = f2tf(w.x); As[kk][mq + 1] = f2tf(w.y);
                As[kk][mq + 2] = f2tf(w.z); As[kk][mq + 3] = f2tf(w.w);
            }
        } else {        // W[M,K]: rows m, contiguous k -> transpose into smem
#pragma unroll
            for (int i = 0; i < 2; i++) {
                int idx = t + 256 * i;          // 0..511
                int m   = idx >> 2;             // 0..127
                int kq  = (idx & 3) << 2;       // 0,4,8,12
                float4 w = *(const float4*)&W[(size_t)(m0 + m) * K + k0 + kq];
                As[kq + 0][m] = f2tf(w.x); As[kq + 1][m] = f2tf(w.y);
                As[kq + 2][m] = f2tf(w.z); As[kq + 3][m] = f2tf(w.w);
            }
        }
        // ---- load B tile (16 x 128) ----
#pragma unroll
        for (int i = 0; i < 2; i++) {
            int idx = t + 256 * i;
            int kk  = idx >> 5;
            int nq  = (idx & 31) << 2;
            float4 x4 = *(const float4*)&Xb[(size_t)(k0 + kk) * N + n0 + nq];
            Bs[kk][nq + 0] = f2tf(x4.x); Bs[kk][nq + 1] = f2tf(x4.y);
            Bs[kk][nq + 2] = f2tf(x4.z); Bs[kk][nq + 3] = f2tf(x4.w);
        }
        __syncthreads();

        // ---- mainloop: 2 k8 steps ----
#pragma unroll
        for (int ks = 0; ks < BK; ks += 8) {
            unsigned bfrag[4][2];
#pragma unroll
            for (int ni = 0; ni < 4; ni++) {
                int nb = wn + 8 * ni + gid;
                bfrag[ni][0] = Bs[ks + tig    ][nb];
                bfrag[ni][1] = Bs[ks + tig + 4][nb];
            }
#pragma unroll
            for (int mi = 0; mi < 4; mi++) {
                int mb = wm + 16 * mi + gid;
                unsigned a0 = As[ks + tig    ][mb];
                unsigned a1 = As[ks + tig    ][mb + 8];
                unsigned a2 = As[ks + tig + 4][mb];
                unsigned a3 = As[ks + tig + 4][mb + 8];
#pragma unroll
                for (int ni = 0; ni < 4; ni++) {
                    asm volatile(
                        "mma.sync.aligned.m16n8k8.row.col.f32.tf32.tf32.f32 "
                        "{%0,%1,%2,%3}, {%4,%5,%6,%7}, {%8,%9}, {%0,%1,%2,%3};"
                        : "+f"(c[mi][ni][0]), "+f"(c[mi][ni][1]),
                          "+f"(c[mi][ni][2]), "+f"(c[mi][ni][3])
                        : "r"(a0), "r"(a1), "r"(a2), "r"(a3),
                          "r"(bfrag[ni][0]), "r"(bfrag[ni][1]));
                }
            }
        }
        __syncthreads();
    }

    // ---- epilogue ----
    float* Yb = Y + (size_t)b * M * N;
    const float* Rb = (EPI == 2) ? res + (size_t)b * M * N : nullptr;
#pragma unroll
    for (int mi = 0; mi < 4; mi++) {
        int mA = m0 + wm + 16 * mi + gid;
        int mB = mA + 8;
        float bvA = __ldg(&bias[mA]);
        float bvB = __ldg(&bias[mB]);
#pragma unroll
        for (int ni = 0; ni < 4; ni++) {
            int n = n0 + wn + 8 * ni + 2 * tig;
            float v0 = c[mi][ni][0] + bvA;
            float v1 = c[mi][ni][1] + bvA;
            float v2 = c[mi][ni][2] + bvB;
            float v3 = c[mi][ni][3] + bvB;
            if (EPI == 1) {
                v0 = 0.5f * v0 * (1.f + erff(v0 * 0.70710678118654752f));
                v1 = 0.5f * v1 * (1.f + erff(v1 * 0.70710678118654752f));
                v2 = 0.5f * v2 * (1.f + erff(v2 * 0.70710678118654752f));
                v3 = 0.5f * v3 * (1.f + erff(v3 * 0.70710678118654752f));
            }
            if (EPI == 2) {
                float2 rA = *(const float2*)&Rb[(size_t)mA * N + n];
                float2 rB = *(const float2*)&Rb[(size_t)mB * N + n];
                v0 += rA.x; v1 += rA.y; v2 += rB.x; v3 += rB.y;
            }
            *(float2*)&Yb[(size_t)mA * N + n] = make_float2(v0, v1);
            *(float2*)&Yb[(size_t)mB * N + n] = make_float2(v2, v3);
        }
    }
}

// ---------------- fused windowed attention ----------------------------------
__global__ __launch_bounds__(128)
void attn_kernel(const float* __restrict__ q, const float* __restrict__ k,
                 const float* __restrict__ v, const float* __restrict__ query,
                 float* __restrict__ out) {
    __shared__ float s1[8][128];
    __shared__ float s2[8][136];
    int tid = threadIdx.x;
    int n0  = blockIdx.x * 128;
    int b   = blockIdx.y;
    int n   = n0 + tid;
    const size_t base = (size_t)b * C_ * N_;

    float acc[KH];
#pragma unroll
    for (int j = 0; j < KH; j++) acc[j] = 0.f;

    for (int c0 = 0; c0 < C_; c0 += 8) {
#pragma unroll
        for (int j = 0; j < 8; j++) {
            s1[j][tid] = q[base + (size_t)(c0 + j) * N_ + n];
            int nn = n0 + tid - PAD;
            s2[j][tid] = (nn >= 0 && nn < N_) ? k[base + (size_t)(c0 + j) * N_ + nn] : 0.f;
        }
        if (tid < 8) {
#pragma unroll
            for (int j = 0; j < 8; j++) {
                int nn = n0 + 128 + tid - PAD;
                s2[j][128 + tid] = (nn < N_) ? k[base + (size_t)(c0 + j) * N_ + nn] : 0.f;
            }
        }
        __syncthreads();
#pragma unroll
        for (int cc = 0; cc < 8; cc++) {
            float qv = s1[cc][tid];
#pragma unroll
            for (int j = 0; j < KH; j++) acc[j] += qv * s2[cc][tid + j];
        }
        __syncthreads();
    }

    float mx = acc[0];
#pragma unroll
    for (int j = 1; j < KH; j++) mx = fmaxf(mx, acc[j]);
    float sum = 0.f;
#pragma unroll
    for (int j = 0; j < KH; j++) { acc[j] = expf(acc[j] - mx); sum += acc[j]; }
    float inv = 0.044194173824159216f / sum;   // 512^-0.5 / sum
#pragma unroll
    for (int j = 0; j < KH; j++) acc[j] *= inv;

    for (int c0 = 0; c0 < C_; c0 += 8) {
#pragma unroll
        for (int j = 0; j < 8; j++) {
            int nn = n0 + tid - PAD;
            s2[j][tid] = (nn >= 0 && nn < N_) ? v[base + (size_t)(c0 + j) * N_ + nn] : 0.f;
        }
        if (tid < 8) {
#pragma unroll
            for (int j = 0; j < 8; j++) {
                int nn = n0 + 128 + tid - PAD;
                s2[j][128 + tid] = (nn < N_) ? v[base + (size_t)(c0 + j) * N_ + nn] : 0.f;
            }
        }
        __syncthreads();
#pragma unroll
        for (int cc = 0; cc < 8; cc++) {
            float r = 0.f;
#pragma unroll
            for (int j = 0; j < KH; j++) r += acc[j] * s2[cc][tid + j];
            size_t idx = base + (size_t)(c0 + cc) * N_ + n;
            out[idx] = query[idx] + r;
        }
        __syncthreads();
    }
}

// ---------------- launch -----------------------------------------------------
extern "C" void kernel_launch(void* const* d_in, const int* in_sizes, int n_in,
                              void* d_out, int out_size) {
    const float* query = (const float*)d_in[0];
    const float* key   = (const float*)d_in[1];
    const float* qe    = (const float*)d_in[2];
    const float* ke    = (const float*)d_in[3];
    const float* wq    = (const float*)d_in[4];
    const float* bq    = (const float*)d_in[5];
    const float* wk    = (const float*)d_in[6];
    const float* bk    = (const float*)d_in[7];
    const float* wv    = (const float*)d_in[8];
    const float* bv    = (const float*)d_in[9];
    const float* gn    = (const float*)d_in[10];
    const float* bn    = (const float*)d_in[11];
    const float* gn2   = (const float*)d_in[12];
    const float* bn2   = (const float*)d_in[13];
    const float* w1    = (const float*)d_in[14];
    const float* b1    = (const float*)d_in[15];
    const float* w2    = (const float*)d_in[16];
    const float* b2    = (const float*)d_in[17];
    float* out = (float*)d_out;

    float *qln, *kln, *qp, *kp, *vp, *xln, *hbuf;
    cudaGetSymbolAddress((void**)&qln,  g_qln);
    cudaGetSymbolAddress((void**)&kln,  g_kln);
    cudaGetSymbolAddress((void**)&qp,   g_qp);
    cudaGetSymbolAddress((void**)&kp,   g_kp);
    cudaGetSymbolAddress((void**)&vp,   g_vp);
    cudaGetSymbolAddress((void**)&xln,  g_xln);
    cudaGetSymbolAddress((void**)&hbuf, g_h);

    dim3 lnGrid(N_ / 256, B_);
    // 1) q/k: add pos-embed + shared LayerNorm
    add_ln_kernel<true><<<lnGrid, 256>>>(query, qe, gn, bn, qln);
    add_ln_kernel<true><<<lnGrid, 256>>>(key,   ke, gn, bn, kln);

    // 2) 1x1 convs (v uses RAW key) — TF32 tensor cores
    dim3 convGrid(N_ / 128, C_ / 128, B_);
    gemm_tc<false, 0><<<convGrid, 256>>>(wq, qln, bq, nullptr, qp, C_, N_, C_);
    gemm_tc<false, 0><<<convGrid, 256>>>(wk, kln, bk, nullptr, kp, C_, N_, C_);
    gemm_tc<false, 0><<<convGrid, 256>>>(wv, key, bv, nullptr, vp, C_, N_, C_);

    // 3) windowed attention + residual  -> d_out holds x
    attn_kernel<<<dim3(N_ / 128, B_), 128>>>(qp, kp, vp, query, out);

    // 4) MLP: pre-LN, fc1+gelu, fc2+residual — TF32 tensor cores
    add_ln_kernel<false><<<lnGrid, 256>>>(out, nullptr, gn2, bn2, xln);
    gemm_tc<true, 1><<<dim3(N_ / 128, MLPH / 128, B_), 256>>>(w1, xln,  b1, nullptr, hbuf, MLPH, N_, C_);
    gemm_tc<true, 2><<<dim3(N_ / 128, C_   / 128, B_), 256>>>(w2, hbuf, b2, out,     out,  C_,   N_, MLPH);
}

// round 10
// speedup vs baseline: 2.0806x; 1.5026x over previous
#include <cuda_runtime.h>
#include <math.h>

#define B_    8
#define C_    512
#define N_    2048
#define KH    9
#define PAD   4
#define MLPH  2048

// ---------------- scratch (device globals: no allocations allowed) ----------
__device__ float g_qln[B_ * C_ * N_];
__device__ float g_kln[B_ * C_ * N_];
__device__ float g_qp [B_ * C_ * N_];
__device__ float g_kp [B_ * C_ * N_];
__device__ float g_vp [B_ * C_ * N_];
__device__ float g_xln[B_ * C_ * N_];
__device__ float g_h  [B_ * MLPH * N_];
// tf32-rounded operand copies
__device__ float g_wqT [C_ * C_];
__device__ float g_wkT [C_ * C_];
__device__ float g_wvT [C_ * C_];
__device__ float g_w1r [C_ * MLPH];
__device__ float g_w2r [MLPH * C_];
__device__ float g_keyr[B_ * C_ * N_];

__device__ __forceinline__ float tf32r(float x) {
    unsigned r; asm("cvt.rna.tf32.f32 %0, %1;" : "=r"(r) : "f"(x));
    return __uint_as_float(r);
}

// ---------------- prep: transpose [M,K] -> [K,M] with tf32 rounding ---------
__global__ void transpose_round(const float* __restrict__ src,
                                float* __restrict__ dst, int M, int K) {
    __shared__ float tile[32][33];
    int k0 = blockIdx.x * 32, m0 = blockIdx.y * 32;
    int tx = threadIdx.x, ty = threadIdx.y;   // 32 x 8
#pragma unroll
    for (int j = 0; j < 32; j += 8)
        tile[ty + j][tx] = src[(size_t)(m0 + ty + j) * K + k0 + tx];
    __syncthreads();
#pragma unroll
    for (int j = 0; j < 32; j += 8)
        dst[(size_t)(k0 + ty + j) * M + m0 + tx] = tf32r(tile[tx][ty + j]);
}

// ---------------- prep: elementwise tf32 round-copy -------------------------
__global__ void round_copy(const float4* __restrict__ src,
                           float4* __restrict__ dst, int n4) {
    int i = blockIdx.x * blockDim.x + threadIdx.x;
    if (i < n4) {
        float4 v = src[i];
        dst[i] = make_float4(tf32r(v.x), tf32r(v.y), tf32r(v.z), tf32r(v.w));
    }
}

// ---------------- fused (optional add) + channel LayerNorm ------------------
// Output is tf32-rounded: LN outputs feed GEMM B operands only.
template<bool HASE>
__global__ void add_ln_kernel(const float* __restrict__ x,
                              const float* __restrict__ e,
                              const float* __restrict__ g,
                              const float* __restrict__ bb,
                              float* __restrict__ out) {
    int n = blockIdx.x * blockDim.x + threadIdx.x;
    int b = blockIdx.y;
    const size_t base = (size_t)b * C_ * N_ + n;
    float s = 0.f, s2 = 0.f;
#pragma unroll 8
    for (int c = 0; c < C_; c++) {
        float v = x[base + (size_t)c * N_];
        if (HASE) v += e[base + (size_t)c * N_];
        s += v; s2 += v * v;
    }
    float mean = s * (1.f / C_);
    float var  = s2 * (1.f / C_) - mean * mean;
    float inv  = rsqrtf(var + 1e-5f);
#pragma unroll 8
    for (int c = 0; c < C_; c++) {
        float v = x[base + (size_t)c * N_];
        if (HASE) v += e[base + (size_t)c * N_];
        out[base + (size_t)c * N_] =
            tf32r((v - mean) * inv * __ldg(&g[c]) + __ldg(&bb[c]));
    }
}

// ---------------- cp.async helpers ------------------------------------------
__device__ __forceinline__ void cp16(void* smem_dst, const void* gmem_src) {
    unsigned d = (unsigned)__cvta_generic_to_shared(smem_dst);
    asm volatile("cp.async.cg.shared.global [%0], [%1], 16;" :: "r"(d), "l"(gmem_src));
}

// ---------------- TF32 tensor-core GEMM, cp.async double-buffered -----------
// Y[b,m,n] = sum_k W[k,m] * X[b,k,n];  W and X are PRE-ROUNDED tf32 bits.
// BM=BN=128, BK=16. 256 threads = 8 warps (2x4), warp tile 64x32,
// per warp 4x4 grid of mma.m16n8k8 (tf32 in, fp32 accum).
// EPI: 0 = +bias, 1 = gelu(+bias) exact + tf32-round store, 2 = +bias+residual.
template<int EPI>
__global__ __launch_bounds__(256)
void gemm_tc(const float* __restrict__ W, const float* __restrict__ X,
             const float* __restrict__ bias, const float* __restrict__ res,
             float* __restrict__ Y, int M, int N, int K) {
    const int BK = 16;
    const int LDS_ = 136;                     // 136 % 32 == 8 -> conflict-free frags
    __shared__ alignas(16) float As[2][BK][LDS_];   // [k][m]
    __shared__ alignas(16) float Bs[2][BK][LDS_];   // [k][n]

    int t    = threadIdx.x;
    int lane = t & 31;
    int warp = t >> 5;
    int gid  = lane >> 2;
    int tig  = lane & 3;
    int wm   = (warp & 1) * 64;
    int wn   = (warp >> 1) * 32;

    int n0 = blockIdx.x * 128;
    int m0 = blockIdx.y * 128;
    int b  = blockIdx.z;
    const float* Xb = X + (size_t)b * K * N;

    float c[4][4][4];
#pragma unroll
    for (int i = 0; i < 4; i++)
#pragma unroll
        for (int j = 0; j < 4; j++)
#pragma unroll
            for (int r = 0; r < 4; r++) c[i][j][r] = 0.f;

    // per-thread cp.async coords: 512 16B-chunks per tile, 2 per thread
    int kkA = t >> 5;                 // rows 0..7 (i=0), 8..15 (i=1)
    int qA  = (t & 31) << 2;          // col (floats), multiple of 4

    auto load_tiles = [&](int s, int k0) {
#pragma unroll
        for (int i = 0; i < 2; i++) {
            int kk = kkA + 8 * i;
            cp16(&As[s][kk][qA], &W [(size_t)(k0 + kk) * M + m0 + qA]);
            cp16(&Bs[s][kk][qA], &Xb[(size_t)(k0 + kk) * N + n0 + qA]);
        }
        asm volatile("cp.async.commit_group;");
    };

    load_tiles(0, 0);
    int s = 0;
    for (int k0 = 0; k0 < K; k0 += BK) {
        if (k0 + BK < K) {
            load_tiles(s ^ 1, k0 + BK);
            asm volatile("cp.async.wait_group 1;");
        } else {
            asm volatile("cp.async.wait_group 0;");
        }
        __syncthreads();

#pragma unroll
        for (int ks = 0; ks < BK; ks += 8) {
            unsigned bfrag[4][2];
#pragma unroll
            for (int ni = 0; ni < 4; ni++) {
                int nb = wn + 8 * ni + gid;
                bfrag[ni][0] = __float_as_uint(Bs[s][ks + tig    ][nb]);
                bfrag[ni][1] = __float_as_uint(Bs[s][ks + tig + 4][nb]);
            }
#pragma unroll
            for (int mi = 0; mi < 4; mi++) {
                int mb = wm + 16 * mi + gid;
                unsigned a0 = __float_as_uint(As[s][ks + tig    ][mb]);
                unsigned a1 = __float_as_uint(As[s][ks + tig    ][mb + 8]);
                unsigned a2 = __float_as_uint(As[s][ks + tig + 4][mb]);
                unsigned a3 = __float_as_uint(As[s][ks + tig + 4][mb + 8]);
#pragma unroll
                for (int ni = 0; ni < 4; ni++) {
                    asm volatile(
                        "mma.sync.aligned.m16n8k8.row.col.f32.tf32.tf32.f32 "
                        "{%0,%1,%2,%3}, {%4,%5,%6,%7}, {%8,%9}, {%0,%1,%2,%3};"
                        : "+f"(c[mi][ni][0]), "+f"(c[mi][ni][1]),
                          "+f"(c[mi][ni][2]), "+f"(c[mi][ni][3])
                        : "r"(a0), "r"(a1), "r"(a2), "r"(a3),
                          "r"(bfrag[ni][0]), "r"(bfrag[ni][1]));
                }
            }
        }
        __syncthreads();
        s ^= 1;
    }

    // ---- epilogue ----
    float* Yb = Y + (size_t)b * M * N;
    const float* Rb = (EPI == 2) ? res + (size_t)b * M * N : nullptr;
#pragma unroll
    for (int mi = 0; mi < 4; mi++) {
        int mA = m0 + wm + 16 * mi + gid;
        int mB = mA + 8;
        float bvA = __ldg(&bias[mA]);
        float bvB = __ldg(&bias[mB]);
#pragma unroll
        for (int ni = 0; ni < 4; ni++) {
            int n = n0 + wn + 8 * ni + 2 * tig;
            float v0 = c[mi][ni][0] + bvA;
            float v1 = c[mi][ni][1] + bvA;
            float v2 = c[mi][ni][2] + bvB;
            float v3 = c[mi][ni][3] + bvB;
            if (EPI == 1) {   // exact gelu, then tf32-round (feeds fc2)
                v0 = tf32r(0.5f * v0 * (1.f + erff(v0 * 0.70710678118654752f)));
                v1 = tf32r(0.5f * v1 * (1.f + erff(v1 * 0.70710678118654752f)));
                v2 = tf32r(0.5f * v2 * (1.f + erff(v2 * 0.70710678118654752f)));
                v3 = tf32r(0.5f * v3 * (1.f + erff(v3 * 0.70710678118654752f)));
            }
            if (EPI == 2) {
                float2 rA = *(const float2*)&Rb[(size_t)mA * N + n];
                float2 rB = *(const float2*)&Rb[(size_t)mB * N + n];
                v0 += rA.x; v1 += rA.y; v2 += rB.x; v3 += rB.y;
            }
            *(float2*)&Yb[(size_t)mA * N + n] = make_float2(v0, v1);
            *(float2*)&Yb[(size_t)mB * N + n] = make_float2(v2, v3);
        }
    }
}

// ---------------- fused windowed attention ----------------------------------
__global__ __launch_bounds__(128)
void attn_kernel(const float* __restrict__ q, const float* __restrict__ k,
                 const float* __restrict__ v, const float* __restrict__ query,
                 float* __restrict__ out) {
    __shared__ float s1[8][128];
    __shared__ float s2[8][136];
    int tid = threadIdx.x;
    int n0  = blockIdx.x * 128;
    int b   = blockIdx.y;
    int n   = n0 + tid;
    const size_t base = (size_t)b * C_ * N_;

    float acc[KH];
#pragma unroll
    for (int j = 0; j < KH; j++) acc[j] = 0.f;

    for (int c0 = 0; c0 < C_; c0 += 8) {
#pragma unroll
        for (int j = 0; j < 8; j++) {
            s1[j][tid] = q[base + (size_t)(c0 + j) * N_ + n];
            int nn = n0 + tid - PAD;
            s2[j][tid] = (nn >= 0 && nn < N_) ? k[base + (size_t)(c0 + j) * N_ + nn] : 0.f;
        }
        if (tid < 8) {
#pragma unroll
            for (int j = 0; j < 8; j++) {
                int nn = n0 + 128 + tid - PAD;
                s2[j][128 + tid] = (nn < N_) ? k[base + (size_t)(c0 + j) * N_ + nn] : 0.f;
            }
        }
        __syncthreads();
#pragma unroll
        for (int cc = 0; cc < 8; cc++) {
            float qv = s1[cc][tid];
#pragma unroll
            for (int j = 0; j < KH; j++) acc[j] += qv * s2[cc][tid + j];
        }
        __syncthreads();
    }

    float mx = acc[0];
#pragma unroll
    for (int j = 1; j < KH; j++) mx = fmaxf(mx, acc[j]);
    float sum = 0.f;
#pragma unroll
    for (int j = 0; j < KH; j++) { acc[j] = expf(acc[j] - mx); sum += acc[j]; }
    float inv = 0.044194173824159216f / sum;   // 512^-0.5 / sum
#pragma unroll
    for (int j = 0; j < KH; j++) acc[j] *= inv;

    for (int c0 = 0; c0 < C_; c0 += 8) {
#pragma unroll
        for (int j = 0; j < 8; j++) {
            int nn = n0 + tid - PAD;
            s2[j][tid] = (nn >= 0 && nn < N_) ? v[base + (size_t)(c0 + j) * N_ + nn] : 0.f;
        }
        if (tid < 8) {
#pragma unroll
            for (int j = 0; j < 8; j++) {
                int nn = n0 + 128 + tid - PAD;
                s2[j][128 + tid] = (nn < N_) ? v[base + (size_t)(c0 + j) * N_ + nn] : 0.f;
            }
        }
        __syncthreads();
#pragma unroll
        for (int cc = 0; cc < 8; cc++) {
            float r = 0.f;
#pragma unroll
            for (int j = 0; j < KH; j++) r += acc[j] * s2[cc][tid + j];
            size_t idx = base + (size_t)(c0 + cc) * N_ + n;
            out[idx] = query[idx] + r;
        }
        __syncthreads();
    }
}

// ---------------- launch -----------------------------------------------------
extern "C" void kernel_launch(void* const* d_in, const int* in_sizes, int n_in,
                              void* d_out, int out_size) {
    const float* query = (const float*)d_in[0];
    const float* key   = (const float*)d_in[1];
    const float* qe    = (const float*)d_in[2];
    const float* ke    = (const float*)d_in[3];
    const float* wq    = (const float*)d_in[4];
    const float* bq    = (const float*)d_in[5];
    const float* wk    = (const float*)d_in[6];
    const float* bk    = (const float*)d_in[7];
    const float* wv    = (const float*)d_in[8];
    const float* bv    = (const float*)d_in[9];
    const float* gn    = (const float*)d_in[10];
    const float* bn    = (const float*)d_in[11];
    const float* gn2   = (const float*)d_in[12];
    const float* bn2   = (const float*)d_in[13];
    const float* w1    = (const float*)d_in[14];
    const float* b1    = (const float*)d_in[15];
    const float* w2    = (const float*)d_in[16];
    const float* b2    = (const float*)d_in[17];
    float* out = (float*)d_out;

    float *qln, *kln, *qp, *kp, *vp, *xln, *hbuf;
    float *wqT, *wkT, *wvT, *w1r, *w2r, *keyr;
    cudaGetSymbolAddress((void**)&qln,  g_qln);
    cudaGetSymbolAddress((void**)&kln,  g_kln);
    cudaGetSymbolAddress((void**)&qp,   g_qp);
    cudaGetSymbolAddress((void**)&kp,   g_kp);
    cudaGetSymbolAddress((void**)&vp,   g_vp);
    cudaGetSymbolAddress((void**)&xln,  g_xln);
    cudaGetSymbolAddress((void**)&hbuf, g_h);
    cudaGetSymbolAddress((void**)&wqT,  g_wqT);
    cudaGetSymbolAddress((void**)&wkT,  g_wkT);
    cudaGetSymbolAddress((void**)&wvT,  g_wvT);
    cudaGetSymbolAddress((void**)&w1r,  g_w1r);
    cudaGetSymbolAddress((void**)&w2r,  g_w2r);
    cudaGetSymbolAddress((void**)&keyr, g_keyr);

    // 0) operand prep: tf32-round every GEMM input that isn't produced rounded
    dim3 tb(32, 8);
    transpose_round<<<dim3(C_ / 32, C_ / 32), tb>>>(wq, wqT, C_, C_);
    transpose_round<<<dim3(C_ / 32, C_ / 32), tb>>>(wk, wkT, C_, C_);
    transpose_round<<<dim3(C_ / 32, C_ / 32), tb>>>(wv, wvT, C_, C_);
    round_copy<<<(C_ * MLPH / 4 + 255) / 256, 256>>>((const float4*)w1, (float4*)w1r, C_ * MLPH / 4);
    round_copy<<<(MLPH * C_ / 4 + 255) / 256, 256>>>((const float4*)w2, (float4*)w2r, MLPH * C_ / 4);
    round_copy<<<(B_ * C_ * N_ / 4 + 255) / 256, 256>>>((const float4*)key, (float4*)keyr, B_ * C_ * N_ / 4);

    dim3 lnGrid(N_ / 256, B_);
    // 1) q/k: add pos-embed + shared LayerNorm (tf32-rounded outputs)
    add_ln_kernel<true><<<lnGrid, 256>>>(query, qe, gn, bn, qln);
    add_ln_kernel<true><<<lnGrid, 256>>>(key,   ke, gn, bn, kln);

    // 2) 1x1 convs (v uses raw key, rounded copy) — TF32 tensor cores
    dim3 convGrid(N_ / 128, C_ / 128, B_);
    gemm_tc<0><<<convGrid, 256>>>(wqT, qln,  bq, nullptr, qp, C_, N_, C_);
    gemm_tc<0><<<convGrid, 256>>>(wkT, kln,  bk, nullptr, kp, C_, N_, C_);
    gemm_tc<0><<<convGrid, 256>>>(wvT, keyr, bv, nullptr, vp, C_, N_, C_);

    // 3) windowed attention + residual  -> d_out holds x
    attn_kernel<<<dim3(N_ / 128, B_), 128>>>(qp, kp, vp, query, out);

    // 4) MLP: pre-LN (rounded), fc1+gelu (rounded out), fc2+residual
    add_ln_kernel<false><<<lnGrid, 256>>>(out, nullptr, gn2, bn2, xln);
    gemm_tc<1><<<dim3(N_ / 128, MLPH / 128, B_), 256>>>(w1r, xln,  b1, nullptr, hbuf, MLPH, N_, C_);
    gemm_tc<2><<<dim3(N_ / 128, C_   / 128, B_), 256>>>(w2r, hbuf, b2, out,     out,  C_,   N_, MLPH);
}

// round 11
// speedup vs baseline: 2.7221x; 1.3083x over previous
#include <cuda_runtime.h>
#include <math.h>

#define B_    8
#define C_    512
#define N_    2048
#define KH    9
#define PAD   4
#define MLPH  2048

// ---------------- scratch (device globals: no allocations allowed) ----------
__device__ float g_qln[B_ * C_ * N_];
__device__ float g_kln[B_ * C_ * N_];
__device__ float g_qp [B_ * C_ * N_];
__device__ float g_kp [B_ * C_ * N_];
__device__ float g_vp [B_ * C_ * N_];
__device__ float g_xln[B_ * C_ * N_];
__device__ float g_h  [B_ * MLPH * N_];
// tf32-rounded operand copies
__device__ float g_wqT [C_ * C_];
__device__ float g_wkT [C_ * C_];
__device__ float g_wvT [C_ * C_];
__device__ float g_w1r [C_ * MLPH];
__device__ float g_w2r [MLPH * C_];
__device__ float g_keyr[B_ * C_ * N_];

__device__ __forceinline__ float tf32r(float x) {
    unsigned r; asm("cvt.rna.tf32.f32 %0, %1;" : "=r"(r) : "f"(x));
    return __uint_as_float(r);
}

// ---------------- prep: transpose [M,K] -> [K,M] with tf32 rounding ---------
__global__ void transpose_round(const float* __restrict__ src,
                                float* __restrict__ dst, int M, int K) {
    __shared__ float tile[32][33];
    int k0 = blockIdx.x * 32, m0 = blockIdx.y * 32;
    int tx = threadIdx.x, ty = threadIdx.y;   // 32 x 8
#pragma unroll
    for (int j = 0; j < 32; j += 8)
        tile[ty + j][tx] = src[(size_t)(m0 + ty + j) * K + k0 + tx];
    __syncthreads();
#pragma unroll
    for (int j = 0; j < 32; j += 8)
        dst[(size_t)(k0 + ty + j) * M + m0 + tx] = tf32r(tile[tx][ty + j]);
}

// ---------------- prep: elementwise tf32 round-copy -------------------------
__global__ void round_copy(const float4* __restrict__ src,
                           float4* __restrict__ dst, int n4) {
    int i = blockIdx.x * blockDim.x + threadIdx.x;
    if (i < n4) {
        float4 v = src[i];
        dst[i] = make_float4(tf32r(v.x), tf32r(v.y), tf32r(v.z), tf32r(v.w));
    }
}

// ---------------- fused (optional add) + channel LayerNorm, 2-phase tiled ---
// Block = (32 n) x (8 c-groups) = 256 threads; grid = (N/32, B) = 512 blocks.
// Output is tf32-rounded (feeds GEMM B operands only).
template<bool HASE>
__global__ __launch_bounds__(256)
void add_ln_kernel(const float* __restrict__ x,
                   const float* __restrict__ e,
                   const float* __restrict__ g,
                   const float* __restrict__ bb,
                   float* __restrict__ out) {
    __shared__ float ps [8][33];
    __shared__ float ps2[8][33];
    __shared__ float smean[32], sinv[32];

    int tx = threadIdx.x & 31;          // n within tile (warp-coalesced)
    int ty = threadIdx.x >> 5;          // c-group 0..7
    int n  = blockIdx.x * 32 + tx;
    int b  = blockIdx.y;
    const size_t base = (size_t)b * C_ * N_ + n;

    float s = 0.f, s2 = 0.f;
#pragma unroll 8
    for (int c = ty; c < C_; c += 8) {
        float v = x[base + (size_t)c * N_];
        if (HASE) v += e[base + (size_t)c * N_];
        s += v; s2 += v * v;
    }
    ps[ty][tx] = s; ps2[ty][tx] = s2;
    __syncthreads();
    if (threadIdx.x < 32) {
        float a = 0.f, a2 = 0.f;
#pragma unroll
        for (int i = 0; i < 8; i++) { a += ps[i][threadIdx.x]; a2 += ps2[i][threadIdx.x]; }
        float mean = a * (1.f / C_);
        float var  = a2 * (1.f / C_) - mean * mean;
        smean[threadIdx.x] = mean;
        sinv [threadIdx.x] = rsqrtf(var + 1e-5f);
    }
    __syncthreads();
    float mean = smean[tx], inv = sinv[tx];
#pragma unroll 8
    for (int c = ty; c < C_; c += 8) {
        float v = x[base + (size_t)c * N_];
        if (HASE) v += e[base + (size_t)c * N_];
        out[base + (size_t)c * N_] =
            tf32r((v - mean) * inv * __ldg(&g[c]) + __ldg(&bb[c]));
    }
}

// ---------------- cp.async helpers ------------------------------------------
__device__ __forceinline__ void cp16(void* smem_dst, const void* gmem_src) {
    unsigned d = (unsigned)__cvta_generic_to_shared(smem_dst);
    asm volatile("cp.async.cg.shared.global [%0], [%1], 16;" :: "r"(d), "l"(gmem_src));
}

// ---------------- TF32 tensor-core GEMM, cp.async double-buffered -----------
// Y[b,m,n] = sum_k W[k,m] * X[b,k,n];  W and X are PRE-ROUNDED tf32 bits.
// BM=BN=128, BK=16. 128 threads = 4 warps (2x2), warp tile 64x64,
// per warp 4x8 grid of mma.m16n8k8 (tf32 in, fp32 accum). LDS/mma = 1.0.
// EPI: 0 = +bias, 1 = gelu(+bias) exact + tf32-round store, 2 = +bias+residual.
template<int EPI>
__global__ __launch_bounds__(128)
void gemm_tc(const float* __restrict__ W, const float* __restrict__ X,
             const float* __restrict__ bias, const float* __restrict__ res,
             float* __restrict__ Y, int M, int N, int K) {
    const int BK = 16;
    const int LDS_ = 136;                     // 136 % 32 == 8 -> conflict-free frags
    __shared__ alignas(16) float As[2][BK][LDS_];   // [k][m]
    __shared__ alignas(16) float Bs[2][BK][LDS_];   // [k][n]

    int t    = threadIdx.x;
    int lane = t & 31;
    int warp = t >> 5;                  // 0..3
    int gid  = lane >> 2;
    int tig  = lane & 3;
    int wm   = (warp & 1) * 64;
    int wn   = (warp >> 1) * 64;

    int n0 = blockIdx.x * 128;
    int m0 = blockIdx.y * 128;
    int b  = blockIdx.z;
    const float* Xb = X + (size_t)b * K * N;

    float c[4][8][4];
#pragma unroll
    for (int i = 0; i < 4; i++)
#pragma unroll
        for (int j = 0; j < 8; j++)
#pragma unroll
            for (int r = 0; r < 4; r++) c[i][j][r] = 0.f;

    // cp.async coords: 512 16B-chunks per tile, 4 per thread per tile
    auto load_tiles = [&](int s, int k0) {
#pragma unroll
        for (int i = 0; i < 4; i++) {
            int idx = t + 128 * i;          // 0..511
            int kk  = idx >> 5;
            int q   = (idx & 31) << 2;
            cp16(&As[s][kk][q], &W [(size_t)(k0 + kk) * M + m0 + q]);
            cp16(&Bs[s][kk][q], &Xb[(size_t)(k0 + kk) * N + n0 + q]);
        }
        asm volatile("cp.async.commit_group;");
    };

    load_tiles(0, 0);
    int s = 0;
    for (int k0 = 0; k0 < K; k0 += BK) {
        if (k0 + BK < K) {
            load_tiles(s ^ 1, k0 + BK);
            asm volatile("cp.async.wait_group 1;");
        } else {
            asm volatile("cp.async.wait_group 0;");
        }
        __syncthreads();

#pragma unroll
        for (int ks = 0; ks < BK; ks += 8) {
            unsigned bfrag[8][2];
#pragma unroll
            for (int ni = 0; ni < 8; ni++) {
                int nb = wn + 8 * ni + gid;
                bfrag[ni][0] = __float_as_uint(Bs[s][ks + tig    ][nb]);
                bfrag[ni][1] = __float_as_uint(Bs[s][ks + tig + 4][nb]);
            }
#pragma unroll
            for (int mi = 0; mi < 4; mi++) {
                int mb = wm + 16 * mi + gid;
                unsigned a0 = __float_as_uint(As[s][ks + tig    ][mb]);
                unsigned a1 = __float_as_uint(As[s][ks + tig    ][mb + 8]);
                unsigned a2 = __float_as_uint(As[s][ks + tig + 4][mb]);
                unsigned a3 = __float_as_uint(As[s][ks + tig + 4][mb + 8]);
#pragma unroll
                for (int ni = 0; ni < 8; ni++) {
                    asm volatile(
                        "mma.sync.aligned.m16n8k8.row.col.f32.tf32.tf32.f32 "
                        "{%0,%1,%2,%3}, {%4,%5,%6,%7}, {%8,%9}, {%0,%1,%2,%3};"
                        : "+f"(c[mi][ni][0]), "+f"(c[mi][ni][1]),
                          "+f"(c[mi][ni][2]), "+f"(c[mi][ni][3])
                        : "r"(a0), "r"(a1), "r"(a2), "r"(a3),
                          "r"(bfrag[ni][0]), "r"(bfrag[ni][1]));
                }
            }
        }
        __syncthreads();
        s ^= 1;
    }

    // ---- epilogue ----
    float* Yb = Y + (size_t)b * M * N;
    const float* Rb = (EPI == 2) ? res + (size_t)b * M * N : nullptr;
#pragma unroll
    for (int mi = 0; mi < 4; mi++) {
        int mA = m0 + wm + 16 * mi + gid;
        int mB = mA + 8;
        float bvA = __ldg(&bias[mA]);
        float bvB = __ldg(&bias[mB]);
#pragma unroll
        for (int ni = 0; ni < 8; ni++) {
            int n = n0 + wn + 8 * ni + 2 * tig;
            float v0 = c[mi][ni][0] + bvA;
            float v1 = c[mi][ni][1] + bvA;
            float v2 = c[mi][ni][2] + bvB;
            float v3 = c[mi][ni][3] + bvB;
            if (EPI == 1) {   // exact gelu, then tf32-round (feeds fc2)
                v0 = tf32r(0.5f * v0 * (1.f + erff(v0 * 0.70710678118654752f)));
                v1 = tf32r(0.5f * v1 * (1.f + erff(v1 * 0.70710678118654752f)));
                v2 = tf32r(0.5f * v2 * (1.f + erff(v2 * 0.70710678118654752f)));
                v3 = tf32r(0.5f * v3 * (1.f + erff(v3 * 0.70710678118654752f)));
            }
            if (EPI == 2) {
                float2 rA = *(const float2*)&Rb[(size_t)mA * N + n];
                float2 rB = *(const float2*)&Rb[(size_t)mB * N + n];
                v0 += rA.x; v1 += rA.y; v2 += rB.x; v3 += rB.y;
            }
            *(float2*)&Yb[(size_t)mA * N + n] = make_float2(v0, v1);
            *(float2*)&Yb[(size_t)mB * N + n] = make_float2(v2, v3);
        }
    }
}

// ---------------- fused windowed attention ----------------------------------
__global__ __launch_bounds__(128)
void attn_kernel(const float* __restrict__ q, const float* __restrict__ k,
                 const float* __restrict__ v, const float* __restrict__ query,
                 float* __restrict__ out) {
    __shared__ float s1[8][128];
    __shared__ float s2[8][136];
    int tid = threadIdx.x;
    int n0  = blockIdx.x * 128;
    int b   = blockIdx.y;
    int n   = n0 + tid;
    const size_t base = (size_t)b * C_ * N_;

    float acc[KH];
#pragma unroll
    for (int j = 0; j < KH; j++) acc[j] = 0.f;

    for (int c0 = 0; c0 < C_; c0 += 8) {
#pragma unroll
        for (int j = 0; j < 8; j++) {
            s1[j][tid] = q[base + (size_t)(c0 + j) * N_ + n];
            int nn = n0 + tid - PAD;
            s2[j][tid] = (nn >= 0 && nn < N_) ? k[base + (size_t)(c0 + j) * N_ + nn] : 0.f;
        }
        if (tid < 8) {
#pragma unroll
            for (int j = 0; j < 8; j++) {
                int nn = n0 + 128 + tid - PAD;
                s2[j][128 + tid] = (nn < N_) ? k[base + (size_t)(c0 + j) * N_ + nn] : 0.f;
            }
        }
        __syncthreads();
#pragma unroll
        for (int cc = 0; cc < 8; cc++) {
            float qv = s1[cc][tid];
#pragma unroll
            for (int j = 0; j < KH; j++) acc[j] += qv * s2[cc][tid + j];
        }
        __syncthreads();
    }

    float mx = acc[0];
#pragma unroll
    for (int j = 1; j < KH; j++) mx = fmaxf(mx, acc[j]);
    float sum = 0.f;
#pragma unroll
    for (int j = 0; j < KH; j++) { acc[j] = expf(acc[j] - mx); sum += acc[j]; }
    float inv = 0.044194173824159216f / sum;   // 512^-0.5 / sum
#pragma unroll
    for (int j = 0; j < KH; j++) acc[j] *= inv;

    for (int c0 = 0; c0 < C_; c0 += 8) {
#pragma unroll
        for (int j = 0; j < 8; j++) {
            int nn = n0 + tid - PAD;
            s2[j][tid] = (nn >= 0 && nn < N_) ? v[base + (size_t)(c0 + j) * N_ + nn] : 0.f;
        }
        if (tid < 8) {
#pragma unroll
            for (int j = 0; j < 8; j++) {
                int nn = n0 + 128 + tid - PAD;
                s2[j][128 + tid] = (nn < N_) ? v[base + (size_t)(c0 + j) * N_ + nn] : 0.f;
            }
        }
        __syncthreads();
#pragma unroll
        for (int cc = 0; cc < 8; cc++) {
            float r = 0.f;
#pragma unroll
            for (int j = 0; j < KH; j++) r += acc[j] * s2[cc][tid + j];
            size_t idx = base + (size_t)(c0 + cc) * N_ + n;
            out[idx] = query[idx] + r;
        }
        __syncthreads();
    }
}

// ---------------- launch -----------------------------------------------------
extern "C" void kernel_launch(void* const* d_in, const int* in_sizes, int n_in,
                              void* d_out, int out_size) {
    const float* query = (const float*)d_in[0];
    const float* key   = (const float*)d_in[1];
    const float* qe    = (const float*)d_in[2];
    const float* ke    = (const float*)d_in[3];
    const float* wq    = (const float*)d_in[4];
    const float* bq    = (const float*)d_in[5];
    const float* wk    = (const float*)d_in[6];
    const float* bk    = (const float*)d_in[7];
    const float* wv    = (const float*)d_in[8];
    const float* bv    = (const float*)d_in[9];
    const float* gn    = (const float*)d_in[10];
    const float* bn    = (const float*)d_in[11];
    const float* gn2   = (const float*)d_in[12];
    const float* bn2   = (const float*)d_in[13];
    const float* w1    = (const float*)d_in[14];
    const float* b1    = (const float*)d_in[15];
    const float* w2    = (const float*)d_in[16];
    const float* b2    = (const float*)d_in[17];
    float* out = (float*)d_out;

    float *qln, *kln, *qp, *kp, *vp, *xln, *hbuf;
    float *wqT, *wkT, *wvT, *w1r, *w2r, *keyr;
    cudaGetSymbolAddress((void**)&qln,  g_qln);
    cudaGetSymbolAddress((void**)&kln,  g_kln);
    cudaGetSymbolAddress((void**)&qp,   g_qp);
    cudaGetSymbolAddress((void**)&kp,   g_kp);
    cudaGetSymbolAddress((void**)&vp,   g_vp);
    cudaGetSymbolAddress((void**)&xln,  g_xln);
    cudaGetSymbolAddress((void**)&hbuf, g_h);
    cudaGetSymbolAddress((void**)&wqT,  g_wqT);
    cudaGetSymbolAddress((void**)&wkT,  g_wkT);
    cudaGetSymbolAddress((void**)&wvT,  g_wvT);
    cudaGetSymbolAddress((void**)&w1r,  g_w1r);
    cudaGetSymbolAddress((void**)&w2r,  g_w2r);
    cudaGetSymbolAddress((void**)&keyr, g_keyr);

    // 0) operand prep: tf32-round every GEMM input that isn't produced rounded
    dim3 tb(32, 8);
    transpose_round<<<dim3(C_ / 32, C_ / 32), tb>>>(wq, wqT, C_, C_);
    transpose_round<<<dim3(C_ / 32, C_ / 32), tb>>>(wk, wkT, C_, C_);
    transpose_round<<<dim3(C_ / 32, C_ / 32), tb>>>(wv, wvT, C_, C_);
    round_copy<<<(C_ * MLPH / 4 + 255) / 256, 256>>>((const float4*)w1, (float4*)w1r, C_ * MLPH / 4);
    round_copy<<<(MLPH * C_ / 4 + 255) / 256, 256>>>((const float4*)w2, (float4*)w2r, MLPH * C_ / 4);
    round_copy<<<(B_ * C_ * N_ / 4 + 255) / 256, 256>>>((const float4*)key, (float4*)keyr, B_ * C_ * N_ / 4);

    dim3 lnGrid(N_ / 32, B_);     // 512 blocks
    // 1) q/k: add pos-embed + shared LayerNorm (tf32-rounded outputs)
    add_ln_kernel<true><<<lnGrid, 256>>>(query, qe, gn, bn, qln);
    add_ln_kernel<true><<<lnGrid, 256>>>(key,   ke, gn, bn, kln);

    // 2) 1x1 convs (v uses raw key, rounded copy) — TF32 tensor cores
    dim3 convGrid(N_ / 128, C_ / 128, B_);
    gemm_tc<0><<<convGrid, 128>>>(wqT, qln,  bq, nullptr, qp, C_, N_, C_);
    gemm_tc<0><<<convGrid, 128>>>(wkT, kln,  bk, nullptr, kp, C_, N_, C_);
    gemm_tc<0><<<convGrid, 128>>>(wvT, keyr, bv, nullptr, vp, C_, N_, C_);

    // 3) windowed attention + residual  -> d_out holds x
    attn_kernel<<<dim3(N_ / 128, B_), 128>>>(qp, kp, vp, query, out);

    // 4) MLP: pre-LN (rounded), fc1+gelu (rounded out), fc2+residual
    add_ln_kernel<false><<<lnGrid, 256>>>(out, nullptr, gn2, bn2, xln);
    gemm_tc<1><<<dim3(N_ / 128, MLPH / 128, B_), 128>>>(w1r, xln,  b1, nullptr, hbuf, MLPH, N_, C_);
    gemm_tc<2><<<dim3(N_ / 128, C_   / 128, B_), 128>>>(w2r, hbuf, b2, out,     out,  C_,   N_, MLPH);
}